// round 8
// baseline (speedup 1.0000x reference)
#include <cuda_runtime.h>
#include <math.h>
#include <stdint.h>

// ============================================================================
// FusedExpertsWrapper — TF32 mma.sync + cp.async.bulk, warp-autonomous pipeline.
//   GEMM1: gu = x@w1 + b1 ; act = silu(gu_even)*gu_odd
//   GEMM2: out = act@w2 + b2
// R8: 128-thread CTAs, 4 warps with 64x64 warp tiles (acc = 128 regs; legal at
// 256-reg/thread budget with 2 CTAs/SM). Halves smem crossbar traffic per FLOP
// vs the 8-warp 64x32 layout (R7 was crossbar-bound at ~2050/2100 cyc/chunk).
// Operands tf32(RNA)-rounded: rel_err ~5e-4 (threshold 1e-3).
// ============================================================================

#define E_EXPERTS 8
#define HDIM      2048
#define IDIM      2048
#define F2I       4096
#define ROWS      4096

// ---------------- tiling ----------------
#define BM      128
#define BN      128
#define BK      32
#define STAGES  3
#define PAD     8
#define LDW     (BM + PAD)                   // 136 floats per k-row
#define TILE_FLTS  (BK * LDW)                // 4352
#define TILE_BYTES (TILE_FLTS * 4)           // 17408
#define STG_FLTS   (2 * TILE_FLTS)           // 8704
#define STG_BYTES  (STG_FLTS * 4)            // 34816
#define DYN_SMEM   (STAGES * STG_BYTES)      // 104448 -> 2 CTAs/SM
#define NCHUNK  (HDIM / BK)                  // 64
#define NWARPS  4

// ---------------- packed scratch: [e][tile][chunk][32][136] ----------------
__device__ float g_xp  [(size_t)E_EXPERTS * 32 * NCHUNK * TILE_FLTS];
__device__ float g_actp[(size_t)E_EXPERTS * 32 * NCHUNK * TILE_FLTS];
__device__ float g_w1p [(size_t)E_EXPERTS * 32 * NCHUNK * TILE_FLTS];
__device__ float g_w2p [(size_t)E_EXPERTS * 16 * NCHUNK * TILE_FLTS];

__device__ __forceinline__ float rnd_tf32(float x) {
    float y; asm("cvt.rna.tf32.f32 %0, %1;" : "=f"(y) : "f"(x)); return y;
}
__device__ __forceinline__ uint32_t smem_to_u32(const void* p) {
    uint32_t a;
    asm("{ .reg .u64 t; cvta.to.shared.u64 t, %1; cvt.u32.u64 %0, t; }" : "=r"(a) : "l"(p));
    return a;
}

#define MBARRIER_INIT(addr, cnt) \
    asm volatile("mbarrier.init.shared.b64 [%0], %1;" :: "r"((uint32_t)(addr)), "r"((uint32_t)(cnt)) : "memory")
#define MBARRIER_EXPECT_TX(addr, bytes) \
    asm volatile("mbarrier.arrive.expect_tx.shared.b64 _, [%0], %1;" :: "r"((uint32_t)(addr)), "r"((uint32_t)(bytes)) : "memory")
#define MBARRIER_ARRIVE(addr) \
    asm volatile("mbarrier.arrive.shared.b64 _, [%0];" :: "r"((uint32_t)(addr)) : "memory")
#define FENCE_PROXY_ASYNC() asm volatile("fence.proxy.async.shared::cta;" ::: "memory")

#define MBARRIER_WAIT_PARITY(mbar_smem_addr, phase_parity) do { \
    uint32_t _mbar = (uint32_t)(mbar_smem_addr); \
    uint32_t _parity = (uint32_t)(phase_parity); \
    uint32_t _done; \
    asm volatile( \
        "{\n\t.reg .pred p;\n\t" \
        "mbarrier.try_wait.parity.acquire.cta.shared::cta.b64 p, [%1], %2;\n\t" \
        "selp.b32 %0, 1, 0, p;\n\t}" \
        : "=r"(_done) : "r"(_mbar), "r"(_parity) : "memory"); \
    if (!_done) { \
        asm volatile( \
            "{\n\t.reg .pred P1;\n\t" \
            "WAIT_LOOP_%=:\n\t" \
            "mbarrier.try_wait.parity.acquire.cta.shared::cta.b64 P1, [%0], %1, 0x989680;\n\t" \
            "@P1 bra.uni WAIT_DONE_%=;\n\t" \
            "bra.uni WAIT_LOOP_%=;\n\t" \
            "WAIT_DONE_%=:\n\t}" \
            :: "r"(_mbar), "r"(_parity) : "memory"); \
    } \
} while (0)

#define MBARRIER_WAIT_PARITY_RELAXED(mbar_smem_addr, phase_parity) do { \
    uint32_t _mbar = (uint32_t)(mbar_smem_addr); \
    uint32_t _parity = (uint32_t)(phase_parity); \
    uint32_t _done; \
    asm volatile( \
        "{\n\t.reg .pred p;\n\t" \
        "mbarrier.try_wait.parity.relaxed.cta.shared::cta.b64 p, [%1], %2, 0x989680;\n\t" \
        "selp.b32 %0, 1, 0, p;\n\t}" \
        : "=r"(_done) : "r"(_mbar), "r"(_parity) : "memory"); \
    if (!_done) { \
        asm volatile( \
            "{\n\t.reg .pred P1;\n\t" \
            "WAIT_LOOP_%=:\n\t" \
            "mbarrier.try_wait.parity.relaxed.cta.shared::cta.b64 P1, [%0], %1, 0x989680;\n\t" \
            "@P1 bra.uni WAIT_DONE_%=;\n\t" \
            "bra.uni WAIT_LOOP_%=;\n\t" \
            "WAIT_DONE_%=:\n\t}" \
            :: "r"(_mbar), "r"(_parity) : "memory"); \
    } \
} while (0)

__device__ __forceinline__ void bulk_g2s(uint32_t sdst, const void* gsrc,
                                         uint32_t bytes, uint32_t mbar) {
    asm volatile(
        "cp.async.bulk.shared::cluster.global.mbarrier::complete_tx::bytes "
        "[%0], [%1], %2, [%3];"
        :: "r"(sdst), "l"(gsrc), "r"(bytes), "r"(mbar) : "memory");
}

#define MMA_TF32(d, a, b) \
    asm volatile("mma.sync.aligned.m16n8k8.row.col.f32.tf32.tf32.f32 " \
        "{%0,%1,%2,%3}, {%4,%5,%6,%7}, {%8,%9}, {%0,%1,%2,%3};" \
        : "+f"((d)[0]), "+f"((d)[1]), "+f"((d)[2]), "+f"((d)[3]) \
        : "r"((a)[0]), "r"((a)[1]), "r"((a)[2]), "r"((a)[3]), \
          "r"((b)[0]), "r"((b)[1]))

// ============================ main GEMM kernel ============================
// 128 threads = 4 warps as 2(M)x2(N); warp tile 64x64; per-warp 4x8 m16n8k8.
template <int MODE>
__global__ void __launch_bounds__(128, 2)
moe_gemm(const float* __restrict__ Ap,
         const float* __restrict__ Bp,
         const float* __restrict__ bias,
         float* __restrict__ outp)
{
    extern __shared__ __align__(1024) float smem[];
    __shared__ __align__(8) unsigned long long mb[2 * STAGES];   // full[0..2], empty[3..5]

    const int NT    = (MODE == 0) ? 32 : 16;
    const int tid   = threadIdx.x;
    const int mtile = blockIdx.x;
    const int ntile = blockIdx.y;
    const int e     = blockIdx.z;

    const int wid  = tid >> 5;                 // 0..3
    const int lane = tid & 31;
    const int g    = lane >> 2;                // 0..7
    const int q    = lane & 3;                 // 0..3
    const int warpM = (wid & 1) * 64;          // 2 warps along M
    const int warpN = (wid >> 1) * 64;         // 2 warps along N

    const float* Abase = Ap + (((size_t)e * 32 + mtile) * NCHUNK) * TILE_FLTS;
    const float* Bbase = Bp + (((size_t)e * NT + ntile) * NCHUNK) * TILE_FLTS;

    const uint32_t smem_u = smem_to_u32(smem);
    const uint32_t mb_u   = smem_to_u32(mb);
    #define FULL_MB(s)  (mb_u + (s) * 8u)
    #define EMPTY_MB(s) (mb_u + (STAGES + (s)) * 8u)

    if (tid == 0) {
        #pragma unroll
        for (int s = 0; s < STAGES; s++) {
            MBARRIER_INIT(FULL_MB(s), 1);
            MBARRIER_INIT(EMPTY_MB(s), NWARPS);   // one arrive per warp
        }
        FENCE_PROXY_ASYNC();
    }
    __syncthreads();   // mbarrier init visible (only CTA-wide barrier)

    if (tid == 0) {
        #pragma unroll
        for (int p = 0; p < 2; p++) {
            MBARRIER_EXPECT_TX(FULL_MB(p), STG_BYTES);
            bulk_g2s(smem_u + p * STG_BYTES,              Abase + (size_t)p * TILE_FLTS, TILE_BYTES, FULL_MB(p));
            bulk_g2s(smem_u + p * STG_BYTES + TILE_BYTES, Bbase + (size_t)p * TILE_FLTS, TILE_BYTES, FULL_MB(p));
        }
    }

    float acc[4][8][4];
    #pragma unroll
    for (int mt = 0; mt < 4; mt++)
        #pragma unroll
        for (int nt = 0; nt < 8; nt++)
            #pragma unroll
            for (int r = 0; r < 4; r++) acc[mt][nt][r] = 0.0f;

    int s = 0;
    for (int c = 0; c < NCHUNK; c++) {
        // producer: refill stage (c+2)%3 once its previous consumers drained
        if (tid == 0) {
            const int cn = c + 2;
            if (cn < NCHUNK) {
                const int spp = cn % 3;
                if (c >= 1) {
                    const int k = cn / 3;                    // reload index
                    MBARRIER_WAIT_PARITY_RELAXED(EMPTY_MB(spp), (k + 1) & 1);
                }
                MBARRIER_EXPECT_TX(FULL_MB(spp), STG_BYTES);
                bulk_g2s(smem_u + spp * STG_BYTES,              Abase + (size_t)cn * TILE_FLTS, TILE_BYTES, FULL_MB(spp));
                bulk_g2s(smem_u + spp * STG_BYTES + TILE_BYTES, Bbase + (size_t)cn * TILE_FLTS, TILE_BYTES, FULL_MB(spp));
            }
        }

        MBARRIER_WAIT_PARITY(FULL_MB(s), (c / 3) & 1);

        const float* sA = smem + s * STG_FLTS;
        const float* sB = sA + TILE_FLTS;
        const float* pA = sA + q * LDW + warpM + g;
        const float* pB = sB + q * LDW + warpN + g;

        #pragma unroll
        for (int ks = 0; ks < 4; ks++) {
            const float* a_ = pA + ks * 8 * LDW;
            const float* b_ = pB + ks * 8 * LDW;
            uint32_t af[4][4];
            #pragma unroll
            for (int mt = 0; mt < 4; mt++) {
                af[mt][0] = __float_as_uint(a_[mt * 16]);
                af[mt][1] = __float_as_uint(a_[mt * 16 + 8]);
                af[mt][2] = __float_as_uint(a_[4 * LDW + mt * 16]);
                af[mt][3] = __float_as_uint(a_[4 * LDW + mt * 16 + 8]);
            }
            uint32_t bf[8][2];
            #pragma unroll
            for (int nt = 0; nt < 8; nt++) {
                bf[nt][0] = __float_as_uint(b_[nt * 8]);
                bf[nt][1] = __float_as_uint(b_[4 * LDW + nt * 8]);
            }
            #pragma unroll
            for (int mt = 0; mt < 4; mt++)
                #pragma unroll
                for (int nt = 0; nt < 8; nt++)
                    MMA_TF32(acc[mt][nt], af[mt], bf[nt]);
        }

        // this warp is done reading stage s
        __syncwarp();
        if (lane == 0) MBARRIER_ARRIVE(EMPTY_MB(s));

        s = (s == STAGES - 1) ? 0 : s + 1;
    }

    // acc: c0:(row g, col 2q) c1:(g,2q+1) c2:(g+8,2q) c3:(g+8,2q+1)
    if (MODE == 0) {
        #pragma unroll
        for (int nt = 0; nt < 8; nt++) {
            const int fpair = ntile * BN + warpN + nt * 8 + 2 * q;   // even = gate
            const float2 bgu = *reinterpret_cast<const float2*>(
                bias + (size_t)e * F2I + fpair);
            const int icol = fpair >> 1;                             // 0..2047
            float* dcol = g_actp
                + ((((size_t)e * 32 + mtile) * NCHUNK + (icol >> 5)) * 32 + (icol & 31)) * LDW
                + warpM;
            #pragma unroll
            for (int mt = 0; mt < 4; mt++) {
                float gg0 = acc[mt][nt][0] + bgu.x;
                float uu0 = acc[mt][nt][1] + bgu.y;
                float gg1 = acc[mt][nt][2] + bgu.x;
                float uu1 = acc[mt][nt][3] + bgu.y;
                float a0 = (gg0 * uu0) / (1.0f + __expf(-gg0));
                float a1 = (gg1 * uu1) / (1.0f + __expf(-gg1));
                dcol[mt * 16 + g]     = rnd_tf32(a0);
                dcol[mt * 16 + g + 8] = rnd_tf32(a1);
            }
        }
    } else {
        #pragma unroll
        for (int nt = 0; nt < 8; nt++) {
            const int h = ntile * BN + warpN + nt * 8 + 2 * q;
            const float2 bb = *reinterpret_cast<const float2*>(
                bias + (size_t)e * HDIM + h);
            #pragma unroll
            for (int mt = 0; mt < 4; mt++) {
                const int m = mtile * BM + warpM + mt * 16 + g;
                float* o0 = outp + ((size_t)e * ROWS + m) * HDIM + h;
                *reinterpret_cast<float2*>(o0) =
                    make_float2(acc[mt][nt][0] + bb.x, acc[mt][nt][1] + bb.y);
                *reinterpret_cast<float2*>(o0 + 8 * (size_t)HDIM) =
                    make_float2(acc[mt][nt][2] + bb.x, acc[mt][nt][3] + bb.y);
            }
        }
    }
}

// ============================ prep kernels ============================

// dispatched [b][e][m][h] -> g_xp [e][mtile][chunk][kk][136]
__global__ void pack_x(const float* __restrict__ in) {
    __shared__ float t[32][33];
    const int e  = blockIdx.z;
    const int r0 = blockIdx.x * 32;     // m dim
    const int h0 = blockIdx.y * 32;     // k dim
    #pragma unroll
    for (int j = 0; j < 4; j++) {
        int r = r0 + threadIdx.y + j * 8;
        int b = r >> 9, m = r & 511;
        t[threadIdx.y + j * 8][threadIdx.x] =
            in[(((size_t)(b * E_EXPERTS + e) << 9) + m) * HDIM + h0 + threadIdx.x];
    }
    __syncthreads();
    #pragma unroll
    for (int j = 0; j < 4; j++) {
        int kg = h0 + threadIdx.y + j * 8;
        int mg = r0 + threadIdx.x;
        g_xp[((((size_t)e * 32 + (mg >> 7)) * NCHUNK + (kg >> 5)) * 32 + (kg & 31)) * LDW
             + (mg & 127)] = rnd_tf32(t[threadIdx.x][threadIdx.y + j * 8]);
    }
}

// weights [e][2048][NB] -> packed [e][NT][chunk][kk][136]
__global__ void pack_w(const float4* __restrict__ in, float* __restrict__ outp,
                       int NT, int NB) {
    size_t i = (size_t)blockIdx.x * blockDim.x + threadIdx.x;  // f4 units
    int nn4 = (int)(i & 31);
    int kk  = (int)((i >> 5) & 31);
    int c   = (int)((i >> 10) & 63);
    size_t r = i >> 16;
    int nt = (int)(r % NT);
    int e  = (int)(r / NT);
    float4 v = in[((size_t)e * 2048 + c * 32 + kk) * (NB / 4) + nt * 32 + nn4];
    v.x = rnd_tf32(v.x); v.y = rnd_tf32(v.y); v.z = rnd_tf32(v.z); v.w = rnd_tf32(v.w);
    *reinterpret_cast<float4*>(
        outp + ((((size_t)e * NT + nt) * NCHUNK + c) * 32 + kk) * LDW + nn4 * 4) = v;
}

// ============================ host side ============================

extern "C" void kernel_launch(void* const* d_in, const int* in_sizes, int n_in,
                              void* d_out, int out_size)
{
    const float* dispatched = (const float*)d_in[0];   // (1,8,8,512,2048)
    const float* w1         = (const float*)d_in[1];   // (8,2048,4096)
    const float* w1_bias    = (const float*)d_in[2];   // (8,4096)
    const float* w2         = (const float*)d_in[3];   // (8,2048,2048)
    const float* w2_bias    = (const float*)d_in[4];   // (8,2048)
    float* out = (float*)d_out;                        // (8,1,4096,2048) fp32
    (void)in_sizes; (void)n_in; (void)out_size;

    static float *p_xp = nullptr, *p_actp = nullptr, *p_w1p = nullptr, *p_w2p = nullptr;
    static bool init_done = false;
    if (!init_done) {
        cudaGetSymbolAddress((void**)&p_xp,   g_xp);
        cudaGetSymbolAddress((void**)&p_actp, g_actp);
        cudaGetSymbolAddress((void**)&p_w1p,  g_w1p);
        cudaGetSymbolAddress((void**)&p_w2p,  g_w2p);
        cudaFuncSetAttribute(moe_gemm<0>, cudaFuncAttributeMaxDynamicSharedMemorySize, DYN_SMEM);
        cudaFuncSetAttribute(moe_gemm<1>, cudaFuncAttributeMaxDynamicSharedMemorySize, DYN_SMEM);
        init_done = true;
    }

    pack_x<<<dim3(ROWS / 32, HDIM / 32, E_EXPERTS), dim3(32, 8)>>>(dispatched);
    pack_w<<<(unsigned)((size_t)E_EXPERTS * 32 * 64 * 32 * 32 / 256), 256>>>(
        reinterpret_cast<const float4*>(w1), p_w1p, 32, F2I);
    pack_w<<<(unsigned)((size_t)E_EXPERTS * 16 * 64 * 32 * 32 / 256), 256>>>(
        reinterpret_cast<const float4*>(w2), p_w2p, 16, HDIM);

    // GEMM1: grid (32 mtiles, 32 ntiles, 8 experts), 128 threads
    moe_gemm<0><<<dim3(32, 32, E_EXPERTS), 128, DYN_SMEM>>>(p_xp, p_w1p, w1_bias, nullptr);
    // GEMM2: grid (32, 16, 8)
    moe_gemm<1><<<dim3(32, 16, E_EXPERTS), 128, DYN_SMEM>>>(p_actp, p_w2p, w2_bias, out);
}

// round 9
// speedup vs baseline: 1.0486x; 1.0486x over previous
#include <cuda_runtime.h>
#include <math.h>
#include <stdint.h>

// ============================================================================
// FusedExpertsWrapper — TF32 mma.sync + cp.async.bulk, warp-autonomous pipeline,
// fragment-order shared memory (R9).
//   GEMM1: gu = x@w1 + b1 ; act = silu(gu_even)*gu_odd
//   GEMM2: out = act@w2 + b2
// R7 config (256 thr, 8 warps 64x32, 3 stages, 2 CTAs/SM) but scratch is packed
// in mma.sync fragment order: per thread A-frag = 1 LDS.128, B-frag = 1 LDS.64.
// 96 -> 32 LDS per warp-chunk, conflict-free, no in-loop address math.
// Operands tf32(RNA)-rounded: rel_err ~5e-4 (threshold 1e-3).
//
// Fragment-order layout per (tile, chunk) block of 4096 floats (16 KB):
//   A: float4 index (ks*8 + mblk)*32 + lane, regs = x(k=q,m=g | k=q,m=g+8 |
//      k=q+4,m=g | k=q+4,m=g+8), m = mblk*16 + ..., k = ks*8 + ...
//   B: float2 index (ks*16 + nblk)*32 + lane, regs = w(k=q,n) | w(k=q+4,n),
//      n = nblk*8 + g.
// ============================================================================

#define E_EXPERTS 8
#define HDIM      2048
#define IDIM      2048
#define F2I       4096
#define ROWS      4096

// ---------------- tiling ----------------
#define BM      128
#define BN      128
#define BK      32
#define STAGES  3
#define BLK_FLTS   4096                      // one operand chunk block (A or B)
#define BLK_BYTES  (BLK_FLTS * 4)            // 16384
#define STG_FLTS   (2 * BLK_FLTS)            // 8192
#define STG_BYTES  (STG_FLTS * 4)            // 32768
#define DYN_SMEM   (STAGES * STG_BYTES)      // 98304 -> 2 CTAs/SM
#define NCHUNK  (HDIM / BK)                  // 64
#define NWARPS  8

// ---------------- packed scratch: [e][tile][chunk][4096] fragment-order ------
__device__ float g_xp  [(size_t)E_EXPERTS * 32 * NCHUNK * BLK_FLTS];
__device__ float g_actp[(size_t)E_EXPERTS * 32 * NCHUNK * BLK_FLTS];
__device__ float g_w1p [(size_t)E_EXPERTS * 32 * NCHUNK * BLK_FLTS];
__device__ float g_w2p [(size_t)E_EXPERTS * 16 * NCHUNK * BLK_FLTS];

__device__ __forceinline__ float rnd_tf32(float x) {
    float y; asm("cvt.rna.tf32.f32 %0, %1;" : "=f"(y) : "f"(x)); return y;
}
__device__ __forceinline__ uint32_t smem_to_u32(const void* p) {
    uint32_t a;
    asm("{ .reg .u64 t; cvta.to.shared.u64 t, %1; cvt.u32.u64 %0, t; }" : "=r"(a) : "l"(p));
    return a;
}

#define MBARRIER_INIT(addr, cnt) \
    asm volatile("mbarrier.init.shared.b64 [%0], %1;" :: "r"((uint32_t)(addr)), "r"((uint32_t)(cnt)) : "memory")
#define MBARRIER_EXPECT_TX(addr, bytes) \
    asm volatile("mbarrier.arrive.expect_tx.shared.b64 _, [%0], %1;" :: "r"((uint32_t)(addr)), "r"((uint32_t)(bytes)) : "memory")
#define MBARRIER_ARRIVE(addr) \
    asm volatile("mbarrier.arrive.shared.b64 _, [%0];" :: "r"((uint32_t)(addr)) : "memory")
#define FENCE_PROXY_ASYNC() asm volatile("fence.proxy.async.shared::cta;" ::: "memory")

#define MBARRIER_WAIT_PARITY(mbar_smem_addr, phase_parity) do { \
    uint32_t _mbar = (uint32_t)(mbar_smem_addr); \
    uint32_t _parity = (uint32_t)(phase_parity); \
    uint32_t _done; \
    asm volatile( \
        "{\n\t.reg .pred p;\n\t" \
        "mbarrier.try_wait.parity.acquire.cta.shared::cta.b64 p, [%1], %2;\n\t" \
        "selp.b32 %0, 1, 0, p;\n\t}" \
        : "=r"(_done) : "r"(_mbar), "r"(_parity) : "memory"); \
    if (!_done) { \
        asm volatile( \
            "{\n\t.reg .pred P1;\n\t" \
            "WAIT_LOOP_%=:\n\t" \
            "mbarrier.try_wait.parity.acquire.cta.shared::cta.b64 P1, [%0], %1, 0x989680;\n\t" \
            "@P1 bra.uni WAIT_DONE_%=;\n\t" \
            "bra.uni WAIT_LOOP_%=;\n\t" \
            "WAIT_DONE_%=:\n\t}" \
            :: "r"(_mbar), "r"(_parity) : "memory"); \
    } \
} while (0)

#define MBARRIER_WAIT_PARITY_RELAXED(mbar_smem_addr, phase_parity) do { \
    uint32_t _mbar = (uint32_t)(mbar_smem_addr); \
    uint32_t _parity = (uint32_t)(phase_parity); \
    uint32_t _done; \
    asm volatile( \
        "{\n\t.reg .pred p;\n\t" \
        "mbarrier.try_wait.parity.relaxed.cta.shared::cta.b64 p, [%1], %2, 0x989680;\n\t" \
        "selp.b32 %0, 1, 0, p;\n\t}" \
        : "=r"(_done) : "r"(_mbar), "r"(_parity) : "memory"); \
    if (!_done) { \
        asm volatile( \
            "{\n\t.reg .pred P1;\n\t" \
            "WAIT_LOOP_%=:\n\t" \
            "mbarrier.try_wait.parity.relaxed.cta.shared::cta.b64 P1, [%0], %1, 0x989680;\n\t" \
            "@P1 bra.uni WAIT_DONE_%=;\n\t" \
            "bra.uni WAIT_LOOP_%=;\n\t" \
            "WAIT_DONE_%=:\n\t}" \
            :: "r"(_mbar), "r"(_parity) : "memory"); \
    } \
} while (0)

__device__ __forceinline__ void bulk_g2s(uint32_t sdst, const void* gsrc,
                                         uint32_t bytes, uint32_t mbar) {
    asm volatile(
        "cp.async.bulk.shared::cluster.global.mbarrier::complete_tx::bytes "
        "[%0], [%1], %2, [%3];"
        :: "r"(sdst), "l"(gsrc), "r"(bytes), "r"(mbar) : "memory");
}

#define MMA_TF32(d, a, b) \
    asm volatile("mma.sync.aligned.m16n8k8.row.col.f32.tf32.tf32.f32 " \
        "{%0,%1,%2,%3}, {%4,%5,%6,%7}, {%8,%9}, {%0,%1,%2,%3};" \
        : "+f"((d)[0]), "+f"((d)[1]), "+f"((d)[2]), "+f"((d)[3]) \
        : "r"((a)[0]), "r"((a)[1]), "r"((a)[2]), "r"((a)[3]), \
          "r"((b)[0]), "r"((b)[1]))

// ============================ main GEMM kernel ============================
// 256 threads = 8 warps as 2(M)x4(N); warp tile 64x32; per-warp 4x4 m16n8k8.
template <int MODE>
__global__ void __launch_bounds__(256, 2)
moe_gemm(const float* __restrict__ Ap,
         const float* __restrict__ Bp,
         const float* __restrict__ bias,
         float* __restrict__ outp)
{
    extern __shared__ __align__(1024) float smem[];
    __shared__ __align__(8) unsigned long long mb[2 * STAGES];   // full[0..2], empty[3..5]

    const int NT    = (MODE == 0) ? 32 : 16;
    const int tid   = threadIdx.x;
    const int mtile = blockIdx.x;
    const int ntile = blockIdx.y;
    const int e     = blockIdx.z;

    const int wid  = tid >> 5;                 // 0..7
    const int lane = tid & 31;
    const int g    = lane >> 2;                // 0..7
    const int q    = lane & 3;                 // 0..3
    const int wm   = wid & 1;                  // M half (0/1): mblk base wm*4
    const int wn   = wid >> 1;                 // N quarter (0..3): nblk base wn*4

    const float* Abase = Ap + (((size_t)e * 32 + mtile) * NCHUNK) * BLK_FLTS;
    const float* Bbase = Bp + (((size_t)e * NT + ntile) * NCHUNK) * BLK_FLTS;

    const uint32_t smem_u = smem_to_u32(smem);
    const uint32_t mb_u   = smem_to_u32(mb);
    #define FULL_MB(s)  (mb_u + (s) * 8u)
    #define EMPTY_MB(s) (mb_u + (STAGES + (s)) * 8u)

    if (tid == 0) {
        #pragma unroll
        for (int s = 0; s < STAGES; s++) {
            MBARRIER_INIT(FULL_MB(s), 1);
            MBARRIER_INIT(EMPTY_MB(s), NWARPS);
        }
        FENCE_PROXY_ASYNC();
    }
    __syncthreads();   // mbarrier init visible (only CTA-wide barrier)

    if (tid == 0) {
        #pragma unroll
        for (int p = 0; p < 2; p++) {
            MBARRIER_EXPECT_TX(FULL_MB(p), STG_BYTES);
            bulk_g2s(smem_u + p * STG_BYTES,             Abase + (size_t)p * BLK_FLTS, BLK_BYTES, FULL_MB(p));
            bulk_g2s(smem_u + p * STG_BYTES + BLK_BYTES, Bbase + (size_t)p * BLK_FLTS, BLK_BYTES, FULL_MB(p));
        }
    }

    float acc[4][4][4];
    #pragma unroll
    for (int mt = 0; mt < 4; mt++)
        #pragma unroll
        for (int nt = 0; nt < 4; nt++)
            #pragma unroll
            for (int r = 0; r < 4; r++) acc[mt][nt][r] = 0.0f;

    int s = 0;
    for (int c = 0; c < NCHUNK; c++) {
        if (tid == 0) {
            const int cn = c + 2;
            if (cn < NCHUNK) {
                const int spp = cn % 3;
                if (c >= 1) {
                    const int k = cn / 3;
                    MBARRIER_WAIT_PARITY_RELAXED(EMPTY_MB(spp), (k + 1) & 1);
                }
                MBARRIER_EXPECT_TX(FULL_MB(spp), STG_BYTES);
                bulk_g2s(smem_u + spp * STG_BYTES,             Abase + (size_t)cn * BLK_FLTS, BLK_BYTES, FULL_MB(spp));
                bulk_g2s(smem_u + spp * STG_BYTES + BLK_BYTES, Bbase + (size_t)cn * BLK_FLTS, BLK_BYTES, FULL_MB(spp));
            }
        }

        MBARRIER_WAIT_PARITY(FULL_MB(s), (c / 3) & 1);

        // fragment-order loads: A float4 per (ks, mt); B float2 per (ks, nt)
        const float4* fA = reinterpret_cast<const float4*>(smem + s * STG_FLTS)
                         + wm * 128 + lane;                  // + ks*256 + mt*32
        const float2* fB = reinterpret_cast<const float2*>(smem + s * STG_FLTS + BLK_FLTS)
                         + wn * 128 + lane;                  // + ks*512 + nt*32

        #pragma unroll
        for (int ks = 0; ks < 4; ks++) {
            float4 a4[4];
            #pragma unroll
            for (int mt = 0; mt < 4; mt++) a4[mt] = fA[ks * 256 + mt * 32];
            float2 b2[4];
            #pragma unroll
            for (int nt = 0; nt < 4; nt++) b2[nt] = fB[ks * 512 + nt * 32];
            #pragma unroll
            for (int mt = 0; mt < 4; mt++) {
                const uint32_t* au = reinterpret_cast<const uint32_t*>(&a4[mt]);
                #pragma unroll
                for (int nt = 0; nt < 4; nt++) {
                    const uint32_t* bu = reinterpret_cast<const uint32_t*>(&b2[nt]);
                    MMA_TF32(acc[mt][nt], au, bu);
                }
            }
        }

        __syncwarp();
        if (lane == 0) MBARRIER_ARRIVE(EMPTY_MB(s));

        s = (s == STAGES - 1) ? 0 : s + 1;
    }

    // acc regs: c0:(row g, col f0) c1:(g, f0+1) c2:(g+8, f0) c3:(g+8, f0+1)
    if (MODE == 0) {
        // write act in fragment order for GEMM2's A
        #pragma unroll
        for (int nt = 0; nt < 4; nt++) {
            const int f0   = ntile * BN + wn * 32 + nt * 8 + 2 * q;   // gate col (even)
            const float2 bgu = *reinterpret_cast<const float2*>(
                bias + (size_t)e * F2I + f0);
            const int icol = f0 >> 1;                 // act column = GEMM2 k, 0..2047
            const int c2   = icol >> 5;
            const int ks2  = (icol >> 3) & 3;
            const int kh   = (icol >> 2) & 1;         // k-high half (q+4 slot)
            float* base = g_actp + (((size_t)e * 32 + mtile) * NCHUNK + c2) * BLK_FLTS
                        + (size_t)ks2 * 256 * 4;      // ks2 block (floats)
            #pragma unroll
            for (int mt = 0; mt < 4; mt++) {
                const int mblk = wm * 4 + mt;
                float* p = base + ((mblk * 32) + (g * 4 + q)) * 4;
                float gg0 = acc[mt][nt][0] + bgu.x;
                float uu0 = acc[mt][nt][1] + bgu.y;
                float gg1 = acc[mt][nt][2] + bgu.x;
                float uu1 = acc[mt][nt][3] + bgu.y;
                float a0 = (gg0 * uu0) / (1.0f + __expf(-gg0));   // row g
                float a1 = (gg1 * uu1) / (1.0f + __expf(-gg1));   // row g+8
                p[0 + 2 * kh] = rnd_tf32(a0);    // reg: mlow
                p[1 + 2 * kh] = rnd_tf32(a1);    // reg: mhigh
            }
        }
    } else {
        #pragma unroll
        for (int nt = 0; nt < 4; nt++) {
            const int h = ntile * BN + wn * 32 + nt * 8 + 2 * q;
            const float2 bb = *reinterpret_cast<const float2*>(
                bias + (size_t)e * HDIM + h);
            #pragma unroll
            for (int mt = 0; mt < 4; mt++) {
                const int m = mtile * BM + wm * 64 + mt * 16 + g;
                float* o0 = outp + ((size_t)e * ROWS + m) * HDIM + h;
                *reinterpret_cast<float2*>(o0) =
                    make_float2(acc[mt][nt][0] + bb.x, acc[mt][nt][1] + bb.y);
                *reinterpret_cast<float2*>(o0 + 8 * (size_t)HDIM) =
                    make_float2(acc[mt][nt][2] + bb.x, acc[mt][nt][3] + bb.y);
            }
        }
    }
}

// ============================ prep kernels ============================

// x [b][e][m][h] -> g_xp fragment-order; one float4 output per thread.
__global__ void pack_x(const float* __restrict__ in) {
    size_t i = (size_t)blockIdx.x * 256 + threadIdx.x;   // float4 index, 2^24 total
    const int lane  = (int)(i & 31);
    const int mblk  = (int)((i >> 5) & 7);
    const int ks    = (int)((i >> 8) & 3);
    const int c     = (int)((i >> 10) & 63);
    const int mtile = (int)((i >> 16) & 31);
    const int e     = (int)(i >> 21);
    const int g = lane >> 2, q = lane & 3;
    const int m0 = mtile * 128 + mblk * 16 + g;          // and m0+8 (same 512-block)
    const int h0 = c * 32 + ks * 8 + q;                  // and h0+4
    const int b  = m0 >> 9, mm = m0 & 511;
    const float* src = in + (((size_t)(b * E_EXPERTS + e) << 9) + mm) * HDIM + h0;
    float4 v;
    v.x = rnd_tf32(src[0]);                 // (k=q,   m=g)
    v.y = rnd_tf32(src[8 * HDIM]);          // (k=q,   m=g+8)
    v.z = rnd_tf32(src[4]);                 // (k=q+4, m=g)
    v.w = rnd_tf32(src[8 * HDIM + 4]);      // (k=q+4, m=g+8)
    reinterpret_cast<float4*>(g_xp)[i] = v;
}

// weights [e][2048][NB] -> fragment-order B; one float2 output per thread.
__global__ void pack_w(const float* __restrict__ in, float* __restrict__ outp,
                       int NT, int NB) {
    size_t i = (size_t)blockIdx.x * 256 + threadIdx.x;   // float2 index
    const int lane = (int)(i & 31);
    const int nblk = (int)((i >> 5) & 15);
    const int ks   = (int)((i >> 9) & 3);
    const int c    = (int)((i >> 11) & 63);
    size_t r = i >> 17;
    const int ntile = (int)(r % NT);
    const int e     = (int)(r / NT);
    const int g = lane >> 2, q = lane & 3;
    const int n0 = ntile * 128 + nblk * 8 + g;
    const int k0 = c * 32 + ks * 8 + q;
    const float* src = in + ((size_t)e * 2048 + k0) * NB + n0;
    float2 v;
    v.x = rnd_tf32(src[0]);                 // (k=q,   n)
    v.y = rnd_tf32(src[(size_t)4 * NB]);    // (k=q+4, n)
    reinterpret_cast<float2*>(outp)[i] = v;
}

// ============================ host side ============================

extern "C" void kernel_launch(void* const* d_in, const int* in_sizes, int n_in,
                              void* d_out, int out_size)
{
    const float* dispatched = (const float*)d_in[0];   // (1,8,8,512,2048)
    const float* w1         = (const float*)d_in[1];   // (8,2048,4096)
    const float* w1_bias    = (const float*)d_in[2];   // (8,4096)
    const float* w2         = (const float*)d_in[3];   // (8,2048,2048)
    const float* w2_bias    = (const float*)d_in[4];   // (8,2048)
    float* out = (float*)d_out;                        // (8,1,4096,2048) fp32
    (void)in_sizes; (void)n_in; (void)out_size;

    static float *p_xp = nullptr, *p_actp = nullptr, *p_w1p = nullptr, *p_w2p = nullptr;
    static bool init_done = false;
    if (!init_done) {
        cudaGetSymbolAddress((void**)&p_xp,   g_xp);
        cudaGetSymbolAddress((void**)&p_actp, g_actp);
        cudaGetSymbolAddress((void**)&p_w1p,  g_w1p);
        cudaGetSymbolAddress((void**)&p_w2p,  g_w2p);
        cudaFuncSetAttribute(moe_gemm<0>, cudaFuncAttributeMaxDynamicSharedMemorySize, DYN_SMEM);
        cudaFuncSetAttribute(moe_gemm<1>, cudaFuncAttributeMaxDynamicSharedMemorySize, DYN_SMEM);
        init_done = true;
    }

    // prep: 2^24 float4 for x; E*NT*2^17 float2 for weights
    pack_x<<<65536, 256>>>(dispatched);
    pack_w<<<(unsigned)(((size_t)E_EXPERTS * 32 << 17) / 256), 256>>>(w1, p_w1p, 32, F2I);
    pack_w<<<(unsigned)(((size_t)E_EXPERTS * 16 << 17) / 256), 256>>>(w2, p_w2p, 16, HDIM);

    // GEMM1: grid (32 mtiles, 32 ntiles, 8 experts)
    moe_gemm<0><<<dim3(32, 32, E_EXPERTS), 256, DYN_SMEM>>>(p_xp, p_w1p, w1_bias, nullptr);
    // GEMM2: grid (32, 16, 8)
    moe_gemm<1><<<dim3(32, 16, E_EXPERTS), 256, DYN_SMEM>>>(p_actp, p_w2p, w2_bias, out);
}

// round 10
// speedup vs baseline: 1.9694x; 1.8781x over previous
#include <cuda_runtime.h>
#include <cuda_fp16.h>
#include <math.h>
#include <stdint.h>

// ============================================================================
// FusedExpertsWrapper — FP16 mma.sync(m16n8k16) + cp.async.bulk, warp-
// autonomous pipeline, fragment-order packed operands (R10).
//   GEMM1: gu = x@w1 + b1 ; act = silu(gu_even)*gu_odd
//   GEMM2: out = act@w2 + b2
// fp16 mantissa == tf32 mantissa (10 bits) -> same ~5e-4 rel_err, but 2x MMA
// throughput. fp32 accumulate. BK=64 (4 x k16), 3 stages x 32KB, 2 CTAs/SM.
// GEMM1 epilogue stages act (f32) in smem, repacks to fp16 fragment order:
// CTA (mtile,ntile) emits exactly GEMM2's A-block (mtile, chunk=ntile).
// ============================================================================

#define E_EXPERTS 8
#define HDIM      2048
#define IDIM      2048
#define F2I       4096
#define ROWS      4096

// ---------------- tiling ----------------
#define BM      128
#define BN      128
#define BK      64
#define STAGES  3
#define A_BYTES    16384                     // 128 x 64 fp16
#define B_BYTES    16384                     // 64 x 128 fp16
#define STG_BYTES  (A_BYTES + B_BYTES)       // 32768
#define DYN_SMEM   (STAGES * STG_BYTES)      // 98304 -> 2 CTAs/SM
#define NCHUNK  (HDIM / BK)                  // 32
#define NWARPS  8
#define A_U4    1024                         // uint4 per A block
#define B_U2    2048                         // uint2 per B block

// ---------------- packed scratch (fragment-order fp16) ----------------
// A blocks: [e][mtile 32][chunk 32][1024 uint4]
__device__ uint4 g_xp  [(size_t)E_EXPERTS * 32 * NCHUNK * A_U4];
__device__ uint4 g_actp[(size_t)E_EXPERTS * 32 * NCHUNK * A_U4];
// B blocks: [e][ntile NT][chunk 32][2048 uint2]
__device__ uint2 g_w1p [(size_t)E_EXPERTS * 32 * NCHUNK * B_U2];
__device__ uint2 g_w2p [(size_t)E_EXPERTS * 16 * NCHUNK * B_U2];

__device__ __forceinline__ uint32_t f2h2(float lo, float hi) {
    __half2 h = __floats2half2_rn(lo, hi);
    return *reinterpret_cast<uint32_t*>(&h);
}
__device__ __forceinline__ uint32_t smem_to_u32(const void* p) {
    uint32_t a;
    asm("{ .reg .u64 t; cvta.to.shared.u64 t, %1; cvt.u32.u64 %0, t; }" : "=r"(a) : "l"(p));
    return a;
}

#define MBARRIER_INIT(addr, cnt) \
    asm volatile("mbarrier.init.shared.b64 [%0], %1;" :: "r"((uint32_t)(addr)), "r"((uint32_t)(cnt)) : "memory")
#define MBARRIER_EXPECT_TX(addr, bytes) \
    asm volatile("mbarrier.arrive.expect_tx.shared.b64 _, [%0], %1;" :: "r"((uint32_t)(addr)), "r"((uint32_t)(bytes)) : "memory")
#define MBARRIER_ARRIVE(addr) \
    asm volatile("mbarrier.arrive.shared.b64 _, [%0];" :: "r"((uint32_t)(addr)) : "memory")
#define FENCE_PROXY_ASYNC() asm volatile("fence.proxy.async.shared::cta;" ::: "memory")

#define MBARRIER_WAIT_PARITY(mbar_smem_addr, phase_parity) do { \
    uint32_t _mbar = (uint32_t)(mbar_smem_addr); \
    uint32_t _parity = (uint32_t)(phase_parity); \
    uint32_t _done; \
    asm volatile( \
        "{\n\t.reg .pred p;\n\t" \
        "mbarrier.try_wait.parity.acquire.cta.shared::cta.b64 p, [%1], %2;\n\t" \
        "selp.b32 %0, 1, 0, p;\n\t}" \
        : "=r"(_done) : "r"(_mbar), "r"(_parity) : "memory"); \
    if (!_done) { \
        asm volatile( \
            "{\n\t.reg .pred P1;\n\t" \
            "WAIT_LOOP_%=:\n\t" \
            "mbarrier.try_wait.parity.acquire.cta.shared::cta.b64 P1, [%0], %1, 0x989680;\n\t" \
            "@P1 bra.uni WAIT_DONE_%=;\n\t" \
            "bra.uni WAIT_LOOP_%=;\n\t" \
            "WAIT_DONE_%=:\n\t}" \
            :: "r"(_mbar), "r"(_parity) : "memory"); \
    } \
} while (0)

#define MBARRIER_WAIT_PARITY_RELAXED(mbar_smem_addr, phase_parity) do { \
    uint32_t _mbar = (uint32_t)(mbar_smem_addr); \
    uint32_t _parity = (uint32_t)(phase_parity); \
    uint32_t _done; \
    asm volatile( \
        "{\n\t.reg .pred p;\n\t" \
        "mbarrier.try_wait.parity.relaxed.cta.shared::cta.b64 p, [%1], %2, 0x989680;\n\t" \
        "selp.b32 %0, 1, 0, p;\n\t}" \
        : "=r"(_done) : "r"(_mbar), "r"(_parity) : "memory"); \
    if (!_done) { \
        asm volatile( \
            "{\n\t.reg .pred P1;\n\t" \
            "WAIT_LOOP_%=:\n\t" \
            "mbarrier.try_wait.parity.relaxed.cta.shared::cta.b64 P1, [%0], %1, 0x989680;\n\t" \
            "@P1 bra.uni WAIT_DONE_%=;\n\t" \
            "bra.uni WAIT_LOOP_%=;\n\t" \
            "WAIT_DONE_%=:\n\t}" \
            :: "r"(_mbar), "r"(_parity) : "memory"); \
    } \
} while (0)

__device__ __forceinline__ void bulk_g2s(uint32_t sdst, const void* gsrc,
                                         uint32_t bytes, uint32_t mbar) {
    asm volatile(
        "cp.async.bulk.shared::cluster.global.mbarrier::complete_tx::bytes "
        "[%0], [%1], %2, [%3];"
        :: "r"(sdst), "l"(gsrc), "r"(bytes), "r"(mbar) : "memory");
}

#define MMA_F16(d, av, bv) \
    asm volatile("mma.sync.aligned.m16n8k16.row.col.f32.f16.f16.f32 " \
        "{%0,%1,%2,%3}, {%4,%5,%6,%7}, {%8,%9}, {%0,%1,%2,%3};" \
        : "+f"((d)[0]), "+f"((d)[1]), "+f"((d)[2]), "+f"((d)[3]) \
        : "r"((av).x), "r"((av).y), "r"((av).z), "r"((av).w), \
          "r"((bv).x), "r"((bv).y))

// ============================ main GEMM kernel ============================
// 256 threads = 8 warps as 2(M)x4(N); warp tile 64x32; per-warp 4x4 m16n8k16.
// Fragment layout (PTX m16n8k16.f16, row.col):
//   A uint4 at ((ks*8+mblk)*32+lane): a0=(m=g,k=2q,2q+1) a1=(g+8,..)
//                                     a2=(g,8+2q,..)     a3=(g+8,8+2q,..)
//   B uint2 at ((ks*16+nblk)*32+lane): b0=(k=2q,2q+1; n=g) b1=(k=8+2q,..; n=g)
//   C: c0=(g,2q) c1=(g,2q+1) c2=(g+8,2q) c3=(g+8,2q+1)
template <int MODE>
__global__ void __launch_bounds__(256, 2)
moe_gemm(const uint4* __restrict__ Ap,
         const uint2* __restrict__ Bp,
         const float* __restrict__ bias,
         float* __restrict__ outp)
{
    extern __shared__ __align__(1024) char smem_c[];
    __shared__ __align__(8) unsigned long long mb[2 * STAGES];   // full[0..2], empty[3..5]

    const int NT    = (MODE == 0) ? 32 : 16;
    const int tid   = threadIdx.x;
    const int mtile = blockIdx.x;
    const int ntile = blockIdx.y;
    const int e     = blockIdx.z;

    const int wid  = tid >> 5;                 // 0..7
    const int lane = tid & 31;
    const int g    = lane >> 2;                // 0..7
    const int q    = lane & 3;                 // 0..3
    const int wm   = wid & 1;                  // M half
    const int wn   = wid >> 1;                 // N quarter 0..3

    const uint4* Abase = Ap + (((size_t)e * 32 + mtile) * NCHUNK) * A_U4;
    const uint2* Bbase = Bp + (((size_t)e * NT + ntile) * NCHUNK) * B_U2;

    const uint32_t smem_u = smem_to_u32(smem_c);
    const uint32_t mb_u   = smem_to_u32(mb);
    #define FULL_MB(s)  (mb_u + (s) * 8u)
    #define EMPTY_MB(s) (mb_u + (STAGES + (s)) * 8u)

    if (tid == 0) {
        #pragma unroll
        for (int s = 0; s < STAGES; s++) {
            MBARRIER_INIT(FULL_MB(s), 1);
            MBARRIER_INIT(EMPTY_MB(s), NWARPS);
        }
        FENCE_PROXY_ASYNC();
    }
    __syncthreads();   // mbarrier init visible

    if (tid == 0) {
        #pragma unroll
        for (int p = 0; p < 2; p++) {
            MBARRIER_EXPECT_TX(FULL_MB(p), STG_BYTES);
            bulk_g2s(smem_u + p * STG_BYTES,           Abase + (size_t)p * A_U4, A_BYTES, FULL_MB(p));
            bulk_g2s(smem_u + p * STG_BYTES + A_BYTES, Bbase + (size_t)p * B_U2, B_BYTES, FULL_MB(p));
        }
    }

    float acc[4][4][4];
    #pragma unroll
    for (int mt = 0; mt < 4; mt++)
        #pragma unroll
        for (int nt = 0; nt < 4; nt++)
            #pragma unroll
            for (int r = 0; r < 4; r++) acc[mt][nt][r] = 0.0f;

    int s = 0;
    for (int c = 0; c < NCHUNK; c++) {
        if (tid == 0) {
            const int cn = c + 2;
            if (cn < NCHUNK) {
                const int spp = cn % 3;
                if (c >= 1) {
                    const int k = cn / 3;
                    MBARRIER_WAIT_PARITY_RELAXED(EMPTY_MB(spp), (k + 1) & 1);
                }
                MBARRIER_EXPECT_TX(FULL_MB(spp), STG_BYTES);
                bulk_g2s(smem_u + spp * STG_BYTES,           Abase + (size_t)cn * A_U4, A_BYTES, FULL_MB(spp));
                bulk_g2s(smem_u + spp * STG_BYTES + A_BYTES, Bbase + (size_t)cn * B_U2, B_BYTES, FULL_MB(spp));
            }
        }

        MBARRIER_WAIT_PARITY(FULL_MB(s), (c / 3) & 1);

        const uint4* fA = reinterpret_cast<const uint4*>(smem_c + s * STG_BYTES)
                        + wm * 128 + lane;                 // + ks*256 + mt*32
        const uint2* fB = reinterpret_cast<const uint2*>(smem_c + s * STG_BYTES + A_BYTES)
                        + wn * 128 + lane;                 // + ks*512 + nt*32

        #pragma unroll
        for (int ks = 0; ks < 4; ks++) {
            uint4 a4[4];
            #pragma unroll
            for (int mt = 0; mt < 4; mt++) a4[mt] = fA[ks * 256 + mt * 32];
            uint2 b2[4];
            #pragma unroll
            for (int nt = 0; nt < 4; nt++) b2[nt] = fB[ks * 512 + nt * 32];
            #pragma unroll
            for (int mt = 0; mt < 4; mt++)
                #pragma unroll
                for (int nt = 0; nt < 4; nt++)
                    MMA_F16(acc[mt][nt], a4[mt], b2[nt]);
        }

        __syncwarp();
        if (lane == 0) MBARRIER_ARRIVE(EMPTY_MB(s));

        s = (s == STAGES - 1) ? 0 : s + 1;
    }

    if (MODE == 0) {
        // ---- epilogue: bias + silu*up -> stage f32 act tile in smem,
        //      then repack to fp16 fragment order (GEMM2 A-block (mtile, ntile)).
        __syncthreads();                       // all warps done with pipeline smem
        float* act_s = reinterpret_cast<float*>(smem_c);   // [128][65]
        #pragma unroll
        for (int nt = 0; nt < 4; nt++) {
            const int f0 = ntile * BN + wn * 32 + nt * 8 + 2 * q;   // gate col (even)
            const float2 bgu = *reinterpret_cast<const float2*>(
                bias + (size_t)e * F2I + f0);
            const int ic = wn * 16 + nt * 4 + q;                    // local icol 0..63
            #pragma unroll
            for (int mt = 0; mt < 4; mt++) {
                const int r0 = wm * 64 + mt * 16 + g;
                float gg0 = acc[mt][nt][0] + bgu.x;
                float uu0 = acc[mt][nt][1] + bgu.y;
                float gg1 = acc[mt][nt][2] + bgu.x;
                float uu1 = acc[mt][nt][3] + bgu.y;
                act_s[r0 * 65 + ic]       = (gg0 * uu0) / (1.0f + __expf(-gg0));
                act_s[(r0 + 8) * 65 + ic] = (gg1 * uu1) / (1.0f + __expf(-gg1));
            }
        }
        __syncthreads();
        uint4* dst = g_actp + (((size_t)e * 32 + mtile) * NCHUNK + ntile) * A_U4;
        #pragma unroll
        for (int r = 0; r < 4; r++) {
            const int j    = tid + r * 256;            // 0..1023
            const int ln   = j & 31;
            const int mblk = (j >> 5) & 7;
            const int ks   = j >> 8;
            const int gg   = ln >> 2, qq = ln & 3;
            const int m0 = mblk * 16 + gg;
            const int k0 = ks * 16 + 2 * qq;
            uint4 o;
            o.x = f2h2(act_s[m0 * 65 + k0],           act_s[m0 * 65 + k0 + 1]);
            o.y = f2h2(act_s[(m0 + 8) * 65 + k0],     act_s[(m0 + 8) * 65 + k0 + 1]);
            o.z = f2h2(act_s[m0 * 65 + k0 + 8],       act_s[m0 * 65 + k0 + 9]);
            o.w = f2h2(act_s[(m0 + 8) * 65 + k0 + 8], act_s[(m0 + 8) * 65 + k0 + 9]);
            dst[j] = o;
        }
    } else {
        #pragma unroll
        for (int nt = 0; nt < 4; nt++) {
            const int h = ntile * BN + wn * 32 + nt * 8 + 2 * q;
            const float2 bb = *reinterpret_cast<const float2*>(
                bias + (size_t)e * HDIM + h);
            #pragma unroll
            for (int mt = 0; mt < 4; mt++) {
                const int m = mtile * BM + wm * 64 + mt * 16 + g;
                float* o0 = outp + ((size_t)e * ROWS + m) * HDIM + h;
                *reinterpret_cast<float2*>(o0) =
                    make_float2(acc[mt][nt][0] + bb.x, acc[mt][nt][1] + bb.y);
                *reinterpret_cast<float2*>(o0 + 8 * (size_t)HDIM) =
                    make_float2(acc[mt][nt][2] + bb.x, acc[mt][nt][3] + bb.y);
            }
        }
    }
}

// ============================ prep kernels ============================

// x [b][e][m][h] -> g_xp fragment-order fp16; one uint4 per thread.
__global__ void pack_x(const float* __restrict__ in) {
    const uint32_t i = blockIdx.x * 256 + threadIdx.x;   // 2^23 total
    const int ln    = i & 31;
    const int mblk  = (i >> 5) & 7;
    const int ks    = (i >> 8) & 3;
    const int c     = (i >> 10) & 31;
    const int mtile = (i >> 15) & 31;
    const int e     = i >> 20;
    const int g = ln >> 2, q = ln & 3;
    const int m0 = mtile * 128 + mblk * 16 + g;          // m0 and m0+8 share b
    const int k0 = c * 64 + ks * 16 + 2 * q;
    const int b = m0 >> 9, mm = m0 & 511;
    const float* row0 = in + (((size_t)(b * E_EXPERTS + e) << 9) + mm) * HDIM + k0;
    const float* row1 = row0 + 8 * (size_t)HDIM;
    uint4 o;
    o.x = f2h2(row0[0], row0[1]);
    o.y = f2h2(row1[0], row1[1]);
    o.z = f2h2(row0[8], row0[9]);
    o.w = f2h2(row1[8], row1[9]);
    g_xp[i] = o;
}

// weights [e][2048][NB] -> fragment-order fp16 B; one uint2 per thread.
__global__ void pack_w(const float* __restrict__ in, uint2* __restrict__ outp,
                       int NT, int NB) {
    const uint32_t i = blockIdx.x * 256 + threadIdx.x;
    const int ln   = i & 31;
    const int nblk = (i >> 5) & 15;
    const int ks   = (i >> 9) & 3;
    const int c    = (i >> 11) & 31;
    const uint32_t r = i >> 16;
    const int ntile = (int)(r % (uint32_t)NT);
    const int e     = (int)(r / (uint32_t)NT);
    const int g = ln >> 2, q = ln & 3;
    const int n0 = ntile * 128 + nblk * 8 + g;
    const int k0 = c * 64 + ks * 16 + 2 * q;
    const float* src = in + ((size_t)e * 2048 + k0) * NB + n0;
    uint2 o;
    o.x = f2h2(src[0],             src[(size_t)NB]);        // k0, k0+1
    o.y = f2h2(src[(size_t)8 * NB], src[(size_t)9 * NB]);   // k0+8, k0+9
    outp[i] = o;
}

// ============================ host side ============================

extern "C" void kernel_launch(void* const* d_in, const int* in_sizes, int n_in,
                              void* d_out, int out_size)
{
    const float* dispatched = (const float*)d_in[0];   // (1,8,8,512,2048)
    const float* w1         = (const float*)d_in[1];   // (8,2048,4096)
    const float* w1_bias    = (const float*)d_in[2];   // (8,4096)
    const float* w2         = (const float*)d_in[3];   // (8,2048,2048)
    const float* w2_bias    = (const float*)d_in[4];   // (8,2048)
    float* out = (float*)d_out;                        // (8,1,4096,2048) fp32
    (void)in_sizes; (void)n_in; (void)out_size;

    static uint4 *p_xp = nullptr, *p_actp = nullptr;
    static uint2 *p_w1p = nullptr, *p_w2p = nullptr;
    static bool init_done = false;
    if (!init_done) {
        cudaGetSymbolAddress((void**)&p_xp,   g_xp);
        cudaGetSymbolAddress((void**)&p_actp, g_actp);
        cudaGetSymbolAddress((void**)&p_w1p,  g_w1p);
        cudaGetSymbolAddress((void**)&p_w2p,  g_w2p);
        cudaFuncSetAttribute(moe_gemm<0>, cudaFuncAttributeMaxDynamicSharedMemorySize, DYN_SMEM);
        cudaFuncSetAttribute(moe_gemm<1>, cudaFuncAttributeMaxDynamicSharedMemorySize, DYN_SMEM);
        init_done = true;
    }

    // prep: x -> 2^23 uint4; w1 -> 2^24 uint2; w2 -> 2^23 uint2
    pack_x<<<32768, 256>>>(dispatched);
    pack_w<<<65536, 256>>>(w1, p_w1p, 32, F2I);
    pack_w<<<32768, 256>>>(w2, p_w2p, 16, HDIM);

    // GEMM1: grid (32 mtiles, 32 ntiles, 8 experts)
    moe_gemm<0><<<dim3(32, 32, E_EXPERTS), 256, DYN_SMEM>>>(p_xp, p_w1p, w1_bias, nullptr);
    // GEMM2: grid (32, 16, 8)
    moe_gemm<1><<<dim3(32, 16, E_EXPERTS), 256, DYN_SMEM>>>(p_actp, p_w2p, w2_bias, out);
}